// round 1
// baseline (speedup 1.0000x reference)
#include <cuda_runtime.h>
#include <math.h>

#define N_TOT   8192
#define NF      8
#define HID     64
#define TILE    64
#define NTHR    256
#define HPITCH  68   // 64 + 4 pad, multiple of 4 for float4 rows

struct GPar { float S1, S2, S3, dens, Kv2, c_r; };
__device__ GPar g_par;

__device__ __forceinline__ float sigm(float x) {
    return 1.0f / (1.0f + __expf(-x));
}

// Accurate-enough tanh: rel err ~1e-6 everywhere (incl. near 0 via poly).
__device__ __forceinline__ float tanh_acc(float x) {
    float ax = fabsf(x);
    if (ax < 0.0625f) {
        float x2 = x * x;
        return x * (1.0f + x2 * (-0.33333333f + x2 * 0.13333334f));
    }
    float e = __expf(-2.0f * ax);
    float r = (1.0f - e) / (1.0f + e);
    return (x < 0.0f) ? -r : r;
}

// ---------------------------------------------------------------------------
// Kernel 0: collapse the 128x32 orientation quadrature to 3 scalar moments,
// and evaluate all sigmoid-bounded scalar parameters. 1 block, 128 threads.
// ---------------------------------------------------------------------------
__global__ void precompute_kernel(const float* __restrict__ nb_raw,
                                  const float* __restrict__ nl_raw,
                                  const float* __restrict__ so_raw,
                                  const float* __restrict__ mg_raw,
                                  const float* __restrict__ s_raw) {
    const float PI = 3.14159265358979f;
    int i = threadIdx.x;  // 0..127 == NTH points
    float sig_o = (10.0f + 70.0f * sigm(so_raw[0])) * (PI / 180.0f);
    float th  = (float)i * (PI * 0.5f / 127.0f);        // linspace(0, pi/2, 128)
    float d   = th - PI * 0.25f;
    float pdf = expf(-d * d / (2.0f * sig_o * sig_o)) * sinf(th);
    float c = cosf(th), s = sinf(th);
    float c2 = c * c, s2 = s * s;

    __shared__ float sh0[128], sh1[128], sh2[128], sh3[128];
    sh0[i] = pdf;
    sh1[i] = pdf * c2 * c2;
    sh2[i] = pdf * c2 * s2;
    sh3[i] = pdf * s2 * s2;
    __syncthreads();

    if (i == 0) {
        float a0 = 0.f, a1 = 0.f, a2 = 0.f, a3 = 0.f;
        for (int j = 0; j < 128; j++) {
            a0 += sh0[j]; a1 += sh1[j]; a2 += sh2[j]; a3 += sh3[j];
        }
        float inv = 1.0f / a0;
        GPar p;
        p.S1 = a1 * inv;  // sum w cos^4
        p.S2 = a2 * inv;  // sum w cos^2 sin^2
        p.S3 = a3 * inv;  // sum w sin^4

        float Nb = exp10f(2.0f + 3.0f * sigm(nb_raw[0]));
        float Nl = exp10f(3.0f + 3.0f * sigm(nl_raw[0]));
        p.dens = Nb * 1e-4f + Nl * 1e-6f;

        float mg   = 0.05f + 0.75f * sigm(mg_raw[0]);
        float epsv = 1.5f + 20.0f * mg;
        float Kv   = (epsv - 1.0f) / (epsv + 2.0f);
        p.Kv2 = Kv * Kv;

        float sm = 0.01f * (0.5f + 5.5f * sigm(s_raw[0]));
        float kw = 2.0f * PI * (5.405e9f / 2.998e8f);   // K_WAVE
        float tt = 2.0f * kw * sm;
        p.c_r = tt * tt;                                 // rough = exp(-c_r*ct^2)

        g_par = p;
    }
}

// ---------------------------------------------------------------------------
// Kernel 1: fused dual MLP (8->64->64->1, tanh) + MIMICS epilogue.
// 128 blocks x 256 threads, 64 samples per block.
// Each thread computes a 4x4 (samples x hidden) micro-tile per layer.
// H staged transposed in smem (HT[col][row]) so layer reads are float4 +
// half-warp broadcast. Weights read via __ldg (L1-resident, 37 KB total).
// ---------------------------------------------------------------------------
__global__ __launch_bounds__(NTHR)
void pinn_kernel(const float* __restrict__ X,
                 const float* __restrict__ theta,
                 const float* __restrict__ Wp1, const float* __restrict__ bp1,
                 const float* __restrict__ Wp2, const float* __restrict__ bp2,
                 const float* __restrict__ Wp3, const float* __restrict__ bp3,
                 const float* __restrict__ Wc1, const float* __restrict__ bc1,
                 const float* __restrict__ Wc2, const float* __restrict__ bc2,
                 const float* __restrict__ Wc3, const float* __restrict__ bc3,
                 float* __restrict__ out) {
    __shared__ float XT[NF][TILE];        // XT[k][r]
    __shared__ float HT[HID][HPITCH];     // HT[col][row], reused H1 -> H2
    __shared__ float Ys[2][TILE];

    const int t = threadIdx.x;
    const int base = blockIdx.x * TILE;

    // stage X transposed
    for (int idx = t; idx < TILE * NF; idx += NTHR) {
        int r = idx >> 3, k = idx & 7;
        XT[k][r] = X[(base + r) * NF + k];
    }
    __syncthreads();

    const int c0 = (t & 15) * 4;   // hidden cols owned
    const int r0 = (t >> 4) * 4;   // sample rows owned

    #pragma unroll
    for (int m = 0; m < 2; m++) {
        const float* W1 = (m == 0) ? Wp1 : Wc1;
        const float* B1 = (m == 0) ? bp1 : bc1;
        const float* W2 = (m == 0) ? Wp2 : Wc2;
        const float* B2 = (m == 0) ? bp2 : bc2;
        const float* W3 = (m == 0) ? Wp3 : Wc3;
        const float* B3 = (m == 0) ? bp3 : bc3;

        float acc[4][4];

        // ---- layer 1: K = 8 ----
        {
            float4 b = __ldg((const float4*)(B1 + c0));
            #pragma unroll
            for (int i = 0; i < 4; i++) {
                acc[i][0] = b.x; acc[i][1] = b.y; acc[i][2] = b.z; acc[i][3] = b.w;
            }
            #pragma unroll
            for (int k = 0; k < NF; k++) {
                float4 a = *(const float4*)&XT[k][r0];
                float4 w = __ldg((const float4*)(W1 + k * HID + c0));
                float av[4] = {a.x, a.y, a.z, a.w};
                float wv[4] = {w.x, w.y, w.z, w.w};
                #pragma unroll
                for (int i = 0; i < 4; i++)
                    #pragma unroll
                    for (int j = 0; j < 4; j++)
                        acc[i][j] = fmaf(av[i], wv[j], acc[i][j]);
            }
            #pragma unroll
            for (int j = 0; j < 4; j++) {
                float4 v;
                v.x = tanh_acc(acc[0][j]); v.y = tanh_acc(acc[1][j]);
                v.z = tanh_acc(acc[2][j]); v.w = tanh_acc(acc[3][j]);
                *(float4*)&HT[c0 + j][r0] = v;
            }
        }
        __syncthreads();

        // ---- layer 2: K = 64 ----
        {
            float4 b = __ldg((const float4*)(B2 + c0));
            #pragma unroll
            for (int i = 0; i < 4; i++) {
                acc[i][0] = b.x; acc[i][1] = b.y; acc[i][2] = b.z; acc[i][3] = b.w;
            }
            #pragma unroll 8
            for (int k = 0; k < HID; k++) {
                float4 a = *(const float4*)&HT[k][r0];
                float4 w = __ldg((const float4*)(W2 + k * HID + c0));
                float av[4] = {a.x, a.y, a.z, a.w};
                float wv[4] = {w.x, w.y, w.z, w.w};
                #pragma unroll
                for (int i = 0; i < 4; i++)
                    #pragma unroll
                    for (int j = 0; j < 4; j++)
                        acc[i][j] = fmaf(av[i], wv[j], acc[i][j]);
            }
        }
        __syncthreads();  // done reading H1
        #pragma unroll
        for (int j = 0; j < 4; j++) {
            float4 v;
            v.x = tanh_acc(acc[0][j]); v.y = tanh_acc(acc[1][j]);
            v.z = tanh_acc(acc[2][j]); v.w = tanh_acc(acc[3][j]);
            *(float4*)&HT[c0 + j][r0] = v;
        }
        __syncthreads();

        // ---- layer 3: 64-long dot per sample ----
        if (t < TILE) {
            float a3 = __ldg(B3);
            #pragma unroll 8
            for (int k = 0; k < HID; k++)
                a3 = fmaf(HT[k][t], __ldg(W3 + k), a3);
            Ys[m][t] = a3;
        }
        __syncthreads();
    }

    // ---- epilogue: MIMICS physics with analytically reduced quadrature ----
    if (t < TILE) {
        const float PI = 3.14159265358979f;
        int s = base + t;
        GPar p = g_par;

        float m_v   = 0.93f * sigm(Ys[0][t]);
        float delta = 0.05f * tanh_acc(Ys[1][t]);
        float eps_g = 3.0f + 25.0f * m_v + 10.0f * m_v * m_v;

        float ti = theta[s] * (PI / 180.0f);
        float ct = cosf(ti), st = sinf(ti);
        float ct2 = ct * ct, st2 = st * st;

        // crown_vv = Kv^2 (ct^4 S1 + 3 ct^2 st^2 S2 + 3/8 st^4 S3)
        // crown_vh = Kv^2 (ct^2 S2 / 2 + st^2 S3 / 8)
        float crown_vv = p.Kv2 * (ct2 * ct2 * p.S1 + 3.0f * ct2 * st2 * p.S2
                                  + 0.375f * st2 * st2 * p.S3);
        float crown_vh = p.Kv2 * (0.5f * ct2 * p.S2 + 0.125f * st2 * p.S3);

        float root  = sqrtf(eps_g - st2);
        float num   = eps_g * ct - root;
        float den   = eps_g * ct + root;
        float r_v   = num / den;
        float gamma = r_v * r_v;
        float rough = expf(-p.c_r * ct2);
        float ground = gamma * rough * ct2;

        float svv = p.dens * crown_vv + ground;
        float svh = p.dens * crown_vh + 0.05f * ground;

        out[0 * N_TOT + s] = m_v;
        out[1 * N_TOT + s] = delta;
        out[2 * N_TOT + s] = m_v + delta;
        out[3 * N_TOT + s] = 10.0f * log10f(svv + 1e-12f);
        out[4 * N_TOT + s] = 10.0f * log10f(svh + 1e-12f);
        out[5 * N_TOT + s] = eps_g;
    }
}

extern "C" void kernel_launch(void* const* d_in, const int* in_sizes, int n_in,
                              void* d_out, int out_size) {
    // inputs: 0 X, 1 theta_inc_deg, 2 vv_db_observed (unused),
    // 3 Wp1, 4 bp1, 5 Wp2, 6 bp2, 7 Wp3, 8 bp3,
    // 9 Wc1, 10 bc1, 11 Wc2, 12 bc2, 13 Wc3, 14 bc3,
    // 15 nb_raw, 16 nl_raw, 17 so_raw, 18 mg_raw, 19 s_raw
    (void)in_sizes; (void)n_in; (void)out_size;

    precompute_kernel<<<1, 128>>>((const float*)d_in[15], (const float*)d_in[16],
                                  (const float*)d_in[17], (const float*)d_in[18],
                                  (const float*)d_in[19]);

    pinn_kernel<<<N_TOT / TILE, NTHR>>>(
        (const float*)d_in[0], (const float*)d_in[1],
        (const float*)d_in[3], (const float*)d_in[4],
        (const float*)d_in[5], (const float*)d_in[6],
        (const float*)d_in[7], (const float*)d_in[8],
        (const float*)d_in[9], (const float*)d_in[10],
        (const float*)d_in[11], (const float*)d_in[12],
        (const float*)d_in[13], (const float*)d_in[14],
        (float*)d_out);
}

// round 2
// speedup vs baseline: 1.5792x; 1.5792x over previous
#include <cuda_runtime.h>
#include <math.h>

#define N_TOT   8192
#define NF      8
#define HID     64
#define TILE    32
#define NTHR    256
#define HP      34   // smem pitch (rows 32 + pad, even for float2)

struct GPar { float S1, S2, S3, dens, Kv2, c_r; };
__device__ GPar g_par;

__device__ __forceinline__ float sigm(float x) {
    return 1.0f / (1.0f + __expf(-x));
}

// Accurate tanh: rel err ~1e-6 everywhere (poly near 0).
__device__ __forceinline__ float tanh_acc(float x) {
    float ax = fabsf(x);
    if (ax < 0.0625f) {
        float x2 = x * x;
        return x * (1.0f + x2 * (-0.33333333f + x2 * 0.13333334f));
    }
    float e = __expf(-2.0f * ax);
    float r = (1.0f - e) / (1.0f + e);
    return (x < 0.0f) ? -r : r;
}

// ---------------------------------------------------------------------------
// Kernel 0: collapse the 128x32 orientation quadrature to 3 scalar moments
// (exact: uniform 32-pt phi-sum of cos^k, k<=4, equals the continuous mean),
// and evaluate all sigmoid-bounded scalar parameters. 1 block, 128 threads.
// ---------------------------------------------------------------------------
__global__ void precompute_kernel(const float* __restrict__ nb_raw,
                                  const float* __restrict__ nl_raw,
                                  const float* __restrict__ so_raw,
                                  const float* __restrict__ mg_raw,
                                  const float* __restrict__ s_raw) {
    const float PI = 3.14159265358979f;
    int i = threadIdx.x;  // 0..127 == NTH points
    float sig_o = (10.0f + 70.0f * sigm(so_raw[0])) * (PI / 180.0f);
    float th  = (float)i * (PI * 0.5f / 127.0f);
    float d   = th - PI * 0.25f;
    float pdf = expf(-d * d / (2.0f * sig_o * sig_o)) * sinf(th);
    float c = cosf(th), s = sinf(th);
    float c2 = c * c, s2 = s * s;

    __shared__ float sh0[128], sh1[128], sh2[128], sh3[128];
    sh0[i] = pdf;
    sh1[i] = pdf * c2 * c2;
    sh2[i] = pdf * c2 * s2;
    sh3[i] = pdf * s2 * s2;
    __syncthreads();

    if (i == 0) {
        float a0 = 0.f, a1 = 0.f, a2 = 0.f, a3 = 0.f;
        for (int j = 0; j < 128; j++) {
            a0 += sh0[j]; a1 += sh1[j]; a2 += sh2[j]; a3 += sh3[j];
        }
        float inv = 1.0f / a0;
        GPar p;
        p.S1 = a1 * inv;
        p.S2 = a2 * inv;
        p.S3 = a3 * inv;

        float Nb = exp10f(2.0f + 3.0f * sigm(nb_raw[0]));
        float Nl = exp10f(3.0f + 3.0f * sigm(nl_raw[0]));
        p.dens = Nb * 1e-4f + Nl * 1e-6f;

        float mg   = 0.05f + 0.75f * sigm(mg_raw[0]);
        float epsv = 1.5f + 20.0f * mg;
        float Kv   = (epsv - 1.0f) / (epsv + 2.0f);
        p.Kv2 = Kv * Kv;

        float sm = 0.01f * (0.5f + 5.5f * sigm(s_raw[0]));
        float kw = 2.0f * PI * (5.405e9f / 2.998e8f);
        float tt = 2.0f * kw * sm;
        p.c_r = tt * tt;

        g_par = p;
    }
}

// ---------------------------------------------------------------------------
// Kernel 1: BOTH MLPs fused into one accumulation pass + MIMICS epilogue.
// 256 blocks x 256 threads, 32 samples per block.
// Microtile per thread: 2 samples x 4 hidden cols x 2 MLPs = 16 accumulators.
// H buffers transposed in smem; weights via __ldg (L1-resident).
// ---------------------------------------------------------------------------
__global__ __launch_bounds__(NTHR, 2)
void pinn_kernel(const float* __restrict__ X,
                 const float* __restrict__ theta,
                 const float* __restrict__ Wp1, const float* __restrict__ bp1,
                 const float* __restrict__ Wp2, const float* __restrict__ bp2,
                 const float* __restrict__ Wp3, const float* __restrict__ bp3,
                 const float* __restrict__ Wc1, const float* __restrict__ bc1,
                 const float* __restrict__ Wc2, const float* __restrict__ bc2,
                 const float* __restrict__ Wc3, const float* __restrict__ bc3,
                 float* __restrict__ out) {
    __shared__ float XT[NF][TILE];       // XT[k][r]
    __shared__ float H1p[HID][HP], H1c[HID][HP];
    __shared__ float H2p[HID][HP], H2c[HID][HP];
    __shared__ float Ys[2][TILE];

    const int t = threadIdx.x;
    const int base = blockIdx.x * TILE;

    // stage X transposed: exactly 256 elements, one per thread
    {
        int r = t >> 3, k = t & 7;
        XT[k][r] = X[(base + r) * NF + k];
    }
    __syncthreads();

    const int c0 = (t & 15) * 4;   // hidden cols owned
    const int r0 = (t >> 4) * 2;   // sample rows owned

    float ap[2][4], ac[2][4];      // accumulators: [row][col] per MLP

    // ---- layer 1 (both MLPs): K = 8 ----
    {
        float4 bp = __ldg((const float4*)(bp1 + c0));
        float4 bc = __ldg((const float4*)(bc1 + c0));
        #pragma unroll
        for (int i = 0; i < 2; i++) {
            ap[i][0] = bp.x; ap[i][1] = bp.y; ap[i][2] = bp.z; ap[i][3] = bp.w;
            ac[i][0] = bc.x; ac[i][1] = bc.y; ac[i][2] = bc.z; ac[i][3] = bc.w;
        }
        #pragma unroll
        for (int k = 0; k < NF; k++) {
            float2 a  = *(const float2*)&XT[k][r0];
            float4 wp = __ldg((const float4*)(Wp1 + k * HID + c0));
            float4 wc = __ldg((const float4*)(Wc1 + k * HID + c0));
            float av[2] = {a.x, a.y};
            float wpv[4] = {wp.x, wp.y, wp.z, wp.w};
            float wcv[4] = {wc.x, wc.y, wc.z, wc.w};
            #pragma unroll
            for (int i = 0; i < 2; i++)
                #pragma unroll
                for (int j = 0; j < 4; j++) {
                    ap[i][j] = fmaf(av[i], wpv[j], ap[i][j]);
                    ac[i][j] = fmaf(av[i], wcv[j], ac[i][j]);
                }
        }
        #pragma unroll
        for (int j = 0; j < 4; j++) {
            float2 vp, vc;
            vp.x = tanh_acc(ap[0][j]); vp.y = tanh_acc(ap[1][j]);
            vc.x = tanh_acc(ac[0][j]); vc.y = tanh_acc(ac[1][j]);
            *(float2*)&H1p[c0 + j][r0] = vp;
            *(float2*)&H1c[c0 + j][r0] = vc;
        }
    }
    __syncthreads();

    // ---- layer 2 (both MLPs): K = 64 ----
    {
        float4 bp = __ldg((const float4*)(bp2 + c0));
        float4 bc = __ldg((const float4*)(bc2 + c0));
        #pragma unroll
        for (int i = 0; i < 2; i++) {
            ap[i][0] = bp.x; ap[i][1] = bp.y; ap[i][2] = bp.z; ap[i][3] = bp.w;
            ac[i][0] = bc.x; ac[i][1] = bc.y; ac[i][2] = bc.z; ac[i][3] = bc.w;
        }
        #pragma unroll 4
        for (int k = 0; k < HID; k++) {
            float2 hp = *(const float2*)&H1p[k][r0];
            float2 hc = *(const float2*)&H1c[k][r0];
            float4 wp = __ldg((const float4*)(Wp2 + k * HID + c0));
            float4 wc = __ldg((const float4*)(Wc2 + k * HID + c0));
            float hpv[2] = {hp.x, hp.y};
            float hcv[2] = {hc.x, hc.y};
            float wpv[4] = {wp.x, wp.y, wp.z, wp.w};
            float wcv[4] = {wc.x, wc.y, wc.z, wc.w};
            #pragma unroll
            for (int i = 0; i < 2; i++)
                #pragma unroll
                for (int j = 0; j < 4; j++) {
                    ap[i][j] = fmaf(hpv[i], wpv[j], ap[i][j]);
                    ac[i][j] = fmaf(hcv[i], wcv[j], ac[i][j]);
                }
        }
        #pragma unroll
        for (int j = 0; j < 4; j++) {
            float2 vp, vc;
            vp.x = tanh_acc(ap[0][j]); vp.y = tanh_acc(ap[1][j]);
            vc.x = tanh_acc(ac[0][j]); vc.y = tanh_acc(ac[1][j]);
            *(float2*)&H2p[c0 + j][r0] = vp;
            *(float2*)&H2c[c0 + j][r0] = vc;
        }
    }
    __syncthreads();

    // ---- layer 3: 64 dot-products (32 samples x 2 MLPs), 64 threads ----
    if (t < 2 * TILE) {
        int mlp = t >> 5, r = t & 31;
        const float* W3 = mlp ? Wc3 : Wp3;
        const float* H2 = mlp ? &H2c[0][0] : &H2p[0][0];
        float s0 = __ldg(mlp ? bc3 : bp3);
        float s1 = 0.f, s2 = 0.f, s3 = 0.f;
        #pragma unroll 4
        for (int k = 0; k < HID; k += 4) {
            s0 = fmaf(H2[(k + 0) * HP + r], __ldg(W3 + k + 0), s0);
            s1 = fmaf(H2[(k + 1) * HP + r], __ldg(W3 + k + 1), s1);
            s2 = fmaf(H2[(k + 2) * HP + r], __ldg(W3 + k + 2), s2);
            s3 = fmaf(H2[(k + 3) * HP + r], __ldg(W3 + k + 3), s3);
        }
        Ys[mlp][r] = (s0 + s1) + (s2 + s3);
    }
    __syncthreads();

    // ---- epilogue: MIMICS physics, analytically reduced quadrature ----
    if (t < TILE) {
        const float PI = 3.14159265358979f;
        int s = base + t;
        GPar p = g_par;

        float m_v   = 0.93f * sigm(Ys[0][t]);
        float delta = 0.05f * tanh_acc(Ys[1][t]);
        float eps_g = 3.0f + 25.0f * m_v + 10.0f * m_v * m_v;

        float ti = theta[s] * (PI / 180.0f);
        float ct = cosf(ti), st = sinf(ti);
        float ct2 = ct * ct, st2 = st * st;

        float crown_vv = p.Kv2 * (ct2 * ct2 * p.S1 + 3.0f * ct2 * st2 * p.S2
                                  + 0.375f * st2 * st2 * p.S3);
        float crown_vh = p.Kv2 * (0.5f * ct2 * p.S2 + 0.125f * st2 * p.S3);

        float root  = sqrtf(eps_g - st2);
        float r_v   = (eps_g * ct - root) / (eps_g * ct + root);
        float gamma = r_v * r_v;
        float rough = expf(-p.c_r * ct2);
        float ground = gamma * rough * ct2;

        float svv = p.dens * crown_vv + ground;
        float svh = p.dens * crown_vh + 0.05f * ground;

        out[0 * N_TOT + s] = m_v;
        out[1 * N_TOT + s] = delta;
        out[2 * N_TOT + s] = m_v + delta;
        out[3 * N_TOT + s] = 10.0f * log10f(svv + 1e-12f);
        out[4 * N_TOT + s] = 10.0f * log10f(svh + 1e-12f);
        out[5 * N_TOT + s] = eps_g;
    }
}

extern "C" void kernel_launch(void* const* d_in, const int* in_sizes, int n_in,
                              void* d_out, int out_size) {
    // inputs: 0 X, 1 theta_inc_deg, 2 vv_db_observed (unused),
    // 3 Wp1, 4 bp1, 5 Wp2, 6 bp2, 7 Wp3, 8 bp3,
    // 9 Wc1, 10 bc1, 11 Wc2, 12 bc2, 13 Wc3, 14 bc3,
    // 15 nb_raw, 16 nl_raw, 17 so_raw, 18 mg_raw, 19 s_raw
    (void)in_sizes; (void)n_in; (void)out_size;

    precompute_kernel<<<1, 128>>>((const float*)d_in[15], (const float*)d_in[16],
                                  (const float*)d_in[17], (const float*)d_in[18],
                                  (const float*)d_in[19]);

    pinn_kernel<<<N_TOT / TILE, NTHR>>>(
        (const float*)d_in[0], (const float*)d_in[1],
        (const float*)d_in[3], (const float*)d_in[4],
        (const float*)d_in[5], (const float*)d_in[6],
        (const float*)d_in[7], (const float*)d_in[8],
        (const float*)d_in[9], (const float*)d_in[10],
        (const float*)d_in[11], (const float*)d_in[12],
        (const float*)d_in[13], (const float*)d_in[14],
        (float*)d_out);
}